// round 1
// baseline (speedup 1.0000x reference)
#include <cuda_runtime.h>
#include <cuda_bf16.h>
#include <math.h>

#define BB 64
#define QQ 2048
#define GG 64
#define CC 128

// ---------------- device scratch (static, no allocation) ----------------
__device__ double g_cost[BB][GG][QQ];          // 64 MB: LSA matrix a[i][j] (row=gt, col=query)
__device__ double g_pn[BB * QQ * 10];          // normalized+clipped bbox preds (float64)
__device__ int    g_pred[BB][GG];              // pred_idx[b][g] = matched query index
__device__ int    g_mlabel[BB][QQ];            // matched label per (b,q) or -1
__device__ double g_part_cls[512];
__device__ double g_part_bbox[BB];
__device__ double g_part_xyz[BB];
__device__ int    g_part_acc[BB];

__constant__ double c_norm[10] = {1.0, 1.0, 1.0, (double)0.1f, (double)0.1f,
                                  (double)0.1f, 1.0, 1.0, (double)0.1f, (double)0.1f};
__constant__ float  c_normf[10] = {1.0f, 1.0f, 1.0f, 0.1f, 0.1f,
                                   0.1f, 1.0f, 1.0f, 0.1f, 0.1f};

// ---------------- phase 1a: normalize+clip bbox preds (float64) ----------------
__global__ __launch_bounds__(256) void pn_kernel(const float* __restrict__ bp) {
    int t = blockIdx.x * 256 + threadIdx.x;       // 0 .. B*Q*10-1
    int k = t % 10;
    double v = (double)bp[t] / c_norm[k];         // correctly-rounded double div, matches numpy
    v = fmin(fmax(v, -100.0), 100.0);
    g_pn[t] = v;
}

// ---------------- phase 1b: cost matrix (float64, numpy-exact ordering) ----------------
__global__ __launch_bounds__(256) void cost_kernel(const float* __restrict__ cs,
                                                   const int* __restrict__ gl,
                                                   const float* __restrict__ gb) {
    int blk = blockIdx.x;             // b*64+g
    int b = blk >> 6, g = blk & 63;
    __shared__ double gn[10];
    __shared__ int slab;
    if (threadIdx.x == 0) slab = gl[b * GG + g];
    if (threadIdx.x < 10) {
        double v = (double)gb[(b * GG + g) * 10 + threadIdx.x] / c_norm[threadIdx.x];
        gn[threadIdx.x] = fmin(fmax(v, -100.0), 100.0);
    }
    __syncthreads();
    int lab = slab;
    const float* csb = cs + (size_t)b * QQ * CC + lab;
    const double* pnb = g_pn + (size_t)b * QQ * 10;
    double* crow = &g_cost[b][g][0];
    double g0 = gn[0], g1 = gn[1], g2 = gn[2], g3 = gn[3], g4 = gn[4];
    double g5 = gn[5], g6 = gn[6], g7 = gn[7], g8 = gn[8], g9 = gn[9];
    for (int q = threadIdx.x; q < QQ; q += 256) {
        double x = (double)csb[(size_t)q * CC];
        x = fmin(fmax(x, -20.0), 20.0);
        double prob = 1.0 / (1.0 + exp(-x));
        const double* pn = pnb + q * 10;
        double d0 = fabs(pn[0] - g0), d1 = fabs(pn[1] - g1);
        double d2 = fabs(pn[2] - g2), d3 = fabs(pn[3] - g3);
        double d4 = fabs(pn[4] - g4), d5 = fabs(pn[5] - g5);
        double d6 = fabs(pn[6] - g6), d7 = fabs(pn[7] - g7);
        double d8 = fabs(pn[8] - g8), d9 = fabs(pn[9] - g9);
        // numpy pairwise-sum order for n=10
        double s = ((d0 + d1) + (d2 + d3)) + ((d4 + d5) + (d6 + d7));
        s = s + d8;
        s = s + d9;
        crow[q] = 2.0 * (-prob) + 0.25 * s;   // both products exact -> FMA-safe
    }
}

// ---------------- phase 2: Jonker-Volgenant LSA, one CTA per batch ----------------
__global__ __launch_bounds__(1024) void lsa_kernel() {
    const int b = blockIdx.x;
    const int tid = threadIdx.x;
    const int lane = tid & 31, warp = tid >> 5;

    __shared__ double sv[QQ + 1];
    __shared__ double sminv[QQ + 1];
    __shared__ double su[GG + 1];
    __shared__ short  sp[QQ + 1];
    __shared__ short  sway[QQ + 1];
    __shared__ unsigned char sused[QQ + 1];
    __shared__ short  slist[GG + 8];
    __shared__ int    scnt, sj0, si0, sbrk, sj1;
    __shared__ double sdelta;
    __shared__ double rval[32];
    __shared__ int    ridx[32];

    for (int j = tid; j <= QQ; j += 1024) { sv[j] = 0.0; sp[j] = 0; sway[j] = 0; }
    if (tid <= GG) su[tid] = 0.0;
    __syncthreads();

    const double* costb = &g_cost[b][0][0];

    for (int i = 1; i <= GG; ++i) {
        for (int j = tid; j <= QQ; j += 1024) { sminv[j] = 1e18; sused[j] = 0; }
        if (tid == 0) { sp[0] = (short)i; sj0 = 0; scnt = 0; }
        __syncthreads();
        while (true) {
            if (tid == 0) {
                int j0 = sj0;
                sused[j0] = 1;
                slist[scnt++] = (short)j0;
                si0 = sp[j0];
            }
            __syncthreads();
            const int i0 = si0;
            const int j0c = sj0;
            const double ui0 = su[i0];
            const double* arow = costb + (size_t)(i0 - 1) * QQ;

            double bv = 1e30;
            int bj = QQ + 2;
#pragma unroll
            for (int rep = 0; rep < 2; ++rep) {
                int j = tid + 1 + rep * 1024;
                if (!sused[j]) {
                    double mv = sminv[j];
                    double cur = (arow[j - 1] - ui0) - sv[j];
                    if (cur < mv) { mv = cur; sminv[j] = cur; sway[j] = (short)j0c; }
                    if (mv < bv) { bv = mv; bj = j; }   // per-thread ascending j -> first-min kept
                }
            }
            // block argmin, lexicographic (value, index) == numpy first-occurrence argmin
            for (int off = 16; off; off >>= 1) {
                double ov = __shfl_down_sync(0xffffffffu, bv, off);
                int    oj = __shfl_down_sync(0xffffffffu, bj, off);
                if (ov < bv || (ov == bv && oj < bj)) { bv = ov; bj = oj; }
            }
            if (lane == 0) { rval[warp] = bv; ridx[warp] = bj; }
            __syncthreads();
            if (warp == 0) {
                bv = rval[lane]; bj = ridx[lane];
                for (int off = 16; off; off >>= 1) {
                    double ov = __shfl_down_sync(0xffffffffu, bv, off);
                    int    oj = __shfl_down_sync(0xffffffffu, bj, off);
                    if (ov < bv || (ov == bv && oj < bj)) { bv = ov; bj = oj; }
                }
                if (lane == 0) { sdelta = bv; sj1 = bj; }
            }
            __syncthreads();
            const double delta = sdelta;
            const int j1 = sj1;
            if (tid < scnt) {                // distinct rows/cols -> no conflicts
                int jj = slist[tid];
                su[sp[jj]] += delta;
                sv[jj] -= delta;
            }
#pragma unroll
            for (int rep = 0; rep < 2; ++rep) {
                int j = tid + 1 + rep * 1024;
                if (!sused[j]) sminv[j] -= delta;
            }
            if (tid == 0) { sj0 = j1; sbrk = (sp[j1] == 0); }
            __syncthreads();
            if (sbrk) break;
        }
        if (tid == 0) {                      // augment
            int j0 = sj0;
            while (j0) { int jn = sway[j0]; sp[j0] = sp[jn]; j0 = jn; }
        }
        __syncthreads();
    }
#pragma unroll
    for (int rep = 0; rep < 2; ++rep) {
        int j = tid + 1 + rep * 1024;
        int pj = sp[j];
        if (pj) g_pred[b][pj - 1] = j - 1;
    }
}

// ---------------- phase 3: losses ----------------
__global__ __launch_bounds__(256) void mlabel_init_kernel() {
    int t = blockIdx.x * 256 + threadIdx.x;
    ((int*)g_mlabel)[t] = -1;
}

__global__ void mlabel_scatter_kernel(const int* __restrict__ gl) {
    int b = blockIdx.x, g = threadIdx.x;
    g_mlabel[b][g_pred[b][g]] = gl[b * GG + g];
}

__global__ __launch_bounds__(256) void losscls_kernel(const float* __restrict__ cs) {
    int t = blockIdx.x * 256 + threadIdx.x;      // (b,q) flattened
    int b = t >> 11, q = t & 2047;
    int ml = g_mlabel[b][q];
    const float4* row = (const float4*)(cs + (size_t)t * CC);
    double acc = 0.0;
#pragma unroll 4
    for (int k = 0; k < CC / 4; ++k) {
        float4 v = row[k];
        float xs[4] = {v.x, v.y, v.z, v.w};
#pragma unroll
        for (int u4 = 0; u4 < 4; ++u4) {
            float x = xs[u4];
            int c = k * 4 + u4;
            float e = __expf(-fabsf(x));
            float inv = 1.0f / (1.0f + e);
            float lp = log1pf(e);                    // log(1+exp(-|x|))
            float p = (x >= 0.0f) ? inv : e * inv;   // sigmoid(x)
            float term;
            if (c == ml) {
                float softm = (x > 0.0f) ? lp : (lp - x);  // softplus(-x)
                float om = 1.0f - p;
                term = softm * 0.25f * om * om;
            } else {
                float softp = (x > 0.0f) ? (x + lp) : lp;  // softplus(x)
                term = softp * 0.75f * p * p;
            }
            acc += (double)term;
        }
    }
    for (int off = 16; off; off >>= 1) acc += __shfl_down_sync(0xffffffffu, acc, off);
    __shared__ double ws[8];
    int lane = threadIdx.x & 31, warp = threadIdx.x >> 5;
    if (lane == 0) ws[warp] = acc;
    __syncthreads();
    if (threadIdx.x == 0) {
        double s = 0.0;
        for (int w = 0; w < 8; ++w) s += ws[w];    // fixed order -> deterministic
        g_part_cls[blockIdx.x] = s;
    }
}

__global__ void bbox_kernel(const float* __restrict__ cs, const float* __restrict__ bp,
                            const int* __restrict__ gl, const float* __restrict__ gb) {
    int b = blockIdx.x, g = threadIdx.x;   // 64 threads
    int q = g_pred[b][g];
    const float* mp = bp + (size_t)(b * QQ + q) * 10;
    const float* mg = gb + (size_t)(b * GG + g) * 10;
    double sb = 0.0, sx = 0.0;
#pragma unroll
    for (int k = 0; k < 10; ++k) {
        float a = mp[k], c2 = mg[k];
        float nr = c_normf[k];
        sb += (double)fabsf(a / nr - c2 / nr);
        if (k < 3) sx += (double)fabsf(a - c2);
    }
    const float* r = cs + (size_t)(b * QQ + q) * CC;
    float best = r[0];
    int bi = 0;
    for (int c2 = 1; c2 < CC; ++c2) { float v = r[c2]; if (v > best) { best = v; bi = c2; } }
    int ok = (bi == gl[b * GG + g]) ? 1 : 0;

    // reduce 64 threads (2 warps), fixed order
    int lane = threadIdx.x & 31, warp = threadIdx.x >> 5;
    for (int off = 16; off; off >>= 1) {
        sb += __shfl_down_sync(0xffffffffu, sb, off);
        sx += __shfl_down_sync(0xffffffffu, sx, off);
        ok += __shfl_down_sync(0xffffffffu, ok, off);
    }
    __shared__ double wsb[2], wsx[2];
    __shared__ int wok[2];
    if (lane == 0) { wsb[warp] = sb; wsx[warp] = sx; wok[warp] = ok; }
    __syncthreads();
    if (threadIdx.x == 0) {
        g_part_bbox[b] = wsb[0] + wsb[1];
        g_part_xyz[b]  = wsx[0] + wsx[1];
        g_part_acc[b]  = wok[0] + wok[1];
    }
}

__global__ void final_kernel(float* __restrict__ out) {
    double s = 0.0;
    for (int i = 0; i < 512; ++i) s += g_part_cls[i];
    double sb = 0.0, sx = 0.0;
    int ac = 0;
    for (int b = 0; b < BB; ++b) { sb += g_part_bbox[b]; sx += g_part_xyz[b]; ac += g_part_acc[b]; }
    out[0] = (float)(s / 4096.0);         // /(G*B)
    out[1] = (float)(sb / 40960.0);       // mean over B*G*10
    out[2] = 64.0f;                       // matched = G
    out[3] = (float)((double)ac / 4096.0);
    out[4] = (float)(sx / 12288.0);       // mean over B*G*3
}

// ---------------- launch ----------------
extern "C" void kernel_launch(void* const* d_in, const int* in_sizes, int n_in,
                              void* d_out, int out_size) {
    const float* cs = (const float*)d_in[0];   // (64,2048,128) f32
    const float* bp = (const float*)d_in[1];   // (64,2048,10)  f32
    const int*   gl = (const int*)d_in[2];     // (64,64)       i32
    const float* gb = (const float*)d_in[3];   // (64,64,10)    f32
    float* out = (float*)d_out;

    pn_kernel<<<(BB * QQ * 10) / 256, 256>>>(bp);
    cost_kernel<<<BB * GG, 256>>>(cs, gl, gb);
    lsa_kernel<<<BB, 1024>>>();
    mlabel_init_kernel<<<(BB * QQ) / 256, 256>>>();
    mlabel_scatter_kernel<<<BB, GG>>>(gl);
    losscls_kernel<<<(BB * QQ) / 256, 256>>>(cs);
    bbox_kernel<<<BB, GG>>>(cs, bp, gl, gb);
    final_kernel<<<1, 1>>>(out);
}